// round 14
// baseline (speedup 1.0000x reference)
#include <cuda_runtime.h>
#include <cuda_bf16.h>
#include <cstdint>

// FlaxHouseholderRoPE: B=2, S=4096, H=32, D=128, R=2, fp32.
// Two kernels overlapped with Programmatic Dependent Launch (PDL):
//   prologue: g_tab (cos/sin per (s,lane), 2MB) via Cody-Waite + MUFU,
//             g_u = v*sqrt(2/(|v|^2+eps)) (normalized reflectors, 32KB);
//             triggers programmatic completion at end of each CTA.
//   main:     R12's proven 75.8us loop. Launched with
//             ProgrammaticStreamSerialization; issues its streamed loads,
//             THEN cudaGridDependencySynchronize() before touching g_tab/g_u,
//             so launch latency + wave-1 loads hide under the prologue.

#define SS 4096
#define HH 32
#define NVEC (2 * SS * HH)        // 262144 vectors per tensor
#define TAB_BLOCKS 512

__device__ float4 g_tab[SS * 32];      // (cos,sin,cos,sin) per (s,lane)
__device__ float4 g_u[HH * 2 * 32];    // normalized reflectors

// inv_freq = 10000^(-i/64): compile-time double-precision table (round 13:
// this choice dropped rel_err to 1.8e-7).
constexpr double R64 = 0.8659643233600653;   // 10000^(-1/64)
constexpr double rpow(int i) {
    double v = 1.0;
    for (int j = 0; j < i; ++j) v *= R64;
    return v;
}
#define FQ(l) { (float)rpow(2*(l)), (float)rpow(2*(l)+1) }
__device__ const float2 g_freq[32] = {
    FQ(0),  FQ(1),  FQ(2),  FQ(3),  FQ(4),  FQ(5),  FQ(6),  FQ(7),
    FQ(8),  FQ(9),  FQ(10), FQ(11), FQ(12), FQ(13), FQ(14), FQ(15),
    FQ(16), FQ(17), FQ(18), FQ(19), FQ(20), FQ(21), FQ(22), FQ(23),
    FQ(24), FQ(25), FQ(26), FQ(27), FQ(28), FQ(29), FQ(30), FQ(31)
};

__device__ __forceinline__ float dot4(float4 a, float4 b) {
    return a.x * b.x + a.y * b.y + a.z * b.z + a.w * b.w;
}

// accurate-enough sincos for a <= 4096: 2-term Cody-Waite + MUFU
__device__ __forceinline__ float2 fast_sincos(float a) {
    const float INV2PI = 0.15915494309189535f;
    const float C1 = 6.28125f;                    // n*C1 exact for n <= 652
    const float C2 = 1.9353071795864769e-3f;      // 2*pi - C1
    const float n = rintf(a * INV2PI);
    float r = fmaf(-n, C1, a);
    r = fmaf(-n, C2, r);
    return make_float2(__cosf(r), __sinf(r));
}

__global__ __launch_bounds__(256)
void prologue_kernel(const float* __restrict__ pos,
                     const float* __restrict__ refl) {
    if (blockIdx.x < TAB_BLOCKS) {
        const int j = blockIdx.x * 256 + threadIdx.x;   // 0 .. 131071
        const int s = j >> 5;
        const int t = j & 31;
        const float p = pos[s];
        const float2 f = g_freq[t];
        const float2 cs0 = fast_sincos(p * f.x);
        const float2 cs1 = fast_sincos(p * f.y);
        g_tab[j] = make_float4(cs0.x, cs0.y, cs1.x, cs1.y);
    } else {
        // one warp per reflector row (h,r): 64 rows over 8 blocks
        const int row  = (blockIdx.x - TAB_BLOCKS) * 8 + ((int)threadIdx.x >> 5);
        const int lane = threadIdx.x & 31;
        if (row < HH * 2) {
            const float4 v = reinterpret_cast<const float4*>(refl)[row * 32 + lane];
            float sq = dot4(v, v);
            #pragma unroll
            for (int o = 16; o; o >>= 1) sq += __shfl_xor_sync(0xffffffffu, sq, o);
            const float sc = sqrtf(2.0f / (sq + 1e-6f));
            g_u[row * 32 + lane] = make_float4(v.x * sc, v.y * sc, v.z * sc, v.w * sc);
        }
    }
    // signal dependent grid (writes above are visible to it after its
    // griddepcontrol.wait)
    cudaTriggerProgrammaticLaunchCompletion();
}

// ===== main kernel: round 12's proven 75.8us loop + grid-dep sync =====
__global__ __launch_bounds__(256)
void hh_rope_kernel(const float* __restrict__ q,
                    const float* __restrict__ k,
                    float* __restrict__ out) {
    const int idx  = (blockIdx.x * blockDim.x + threadIdx.x) >> 5;  // (b*S+s)*H + h
    const int lane = threadIdx.x & 31;

    const int h = idx & (HH - 1);
    const int s = (idx >> 5) & (SS - 1);

    const size_t off = (size_t)idx * 32 + lane;

    // streamed loads first — independent of the prologue, overlap its tail
    float4 xq = __ldcs(reinterpret_cast<const float4*>(q) + off);
    float4 xk = __ldcs(reinterpret_cast<const float4*>(k) + off);

    // wait for prologue's g_tab / g_u to be visible
    cudaGridDependencySynchronize();

    // two sequential normalized-Householder reflections on q and k
    #pragma unroll
    for (int r = 0; r < 2; ++r) {
        const float4 u = g_u[(h * 2 + r) * 32 + lane];   // L1 hit
        float dq = dot4(xq, u);
        float dk = dot4(xk, u);
        #pragma unroll
        for (int o = 16; o; o >>= 1) {
            dq += __shfl_xor_sync(0xffffffffu, dq, o);
            dk += __shfl_xor_sync(0xffffffffu, dk, o);
        }
        xq.x -= dq * u.x;  xq.y -= dq * u.y;  xq.z -= dq * u.z;  xq.w -= dq * u.w;
        xk.x -= dk * u.x;  xk.y -= dk * u.y;  xk.z -= dk * u.z;  xk.w -= dk * u.w;
    }

    // RoPE via table (same row across the block's 8 warps -> L1 broadcast)
    const float4 cs = g_tab[s * 32 + lane];   // (c0, s0, c1, s1)

    float4 oq, ok;
    oq.x = xq.x * cs.x - xq.y * cs.y;
    oq.y = xq.x * cs.y + xq.y * cs.x;
    oq.z = xq.z * cs.z - xq.w * cs.w;
    oq.w = xq.z * cs.w + xq.w * cs.z;
    ok.x = xk.x * cs.x - xk.y * cs.y;
    ok.y = xk.x * cs.y + xk.y * cs.x;
    ok.z = xk.z * cs.z - xk.w * cs.w;
    ok.w = xk.z * cs.w + xk.w * cs.z;

    float4* out4 = reinterpret_cast<float4*>(out);
    __stcs(out4 + off, oq);                              // q half
    __stcs(out4 + (size_t)NVEC * 32 + off, ok);          // k half
}

extern "C" void kernel_launch(void* const* d_in, const int* in_sizes, int n_in,
                              void* d_out, int out_size) {
    const float* q    = (const float*)d_in[0];
    const float* k    = (const float*)d_in[1];
    const float* pos  = (const float*)d_in[2];
    const float* refl = (const float*)d_in[3];
    float* out = (float*)d_out;

    // prologue: normal launch
    prologue_kernel<<<TAB_BLOCKS + 8, 256>>>(pos, refl);

    // main: PDL launch — may start while prologue is still running
    cudaLaunchConfig_t cfg = {};
    cfg.gridDim  = dim3(NVEC / 8, 1, 1);     // 32768 blocks
    cfg.blockDim = dim3(256, 1, 1);
    cfg.dynamicSmemBytes = 0;
    cfg.stream = 0;
    cudaLaunchAttribute attr[1];
    attr[0].id = cudaLaunchAttributeProgrammaticStreamSerialization;
    attr[0].val.programmaticStreamSerializationAllowed = 1;
    cfg.attrs = attr;
    cfg.numAttrs = 1;
    cudaLaunchKernelEx(&cfg, hh_rope_kernel, q, k, out);
}